// round 1
// baseline (speedup 1.0000x reference)
#include <cuda_runtime.h>
#include <cstdint>

#define Bn 16
#define Cn 64
#define Hn 192
#define Wn 192
#define HCH 8
#define HW (Hn*Wn)                 // 36864
#define Z_ELEMS (Bn*Cn*HW)         // 37748736
#define HC_ELEMS (Bn*HCH*HW)       // 4718592
#define KTOT (Cn + HCH)            // 72
#define QPB  (HW/4)                // pixel-quads per batch = 9216

// scratch: u/v partial sums (96 floats) + fallback hidden/cell storage
__device__ float g_uvsum[96];
__device__ float g_hid_scratch[HC_ELEMS];
__device__ float g_cell_scratch[HC_ELEMS];

// ---------- helpers ----------
__device__ __forceinline__ unsigned long long pack2(float lo, float hi) {
    unsigned long long r;
    asm("mov.b64 %0, {%1, %2};" : "=l"(r) : "f"(lo), "f"(hi));
    return r;
}
__device__ __forceinline__ float2 unpack2(unsigned long long v) {
    float lo, hi;
    asm("mov.b64 {%0, %1}, %2;" : "=f"(lo), "=f"(hi) : "l"(v));
    return make_float2(lo, hi);
}
__device__ __forceinline__ unsigned long long ffma2(unsigned long long a,
                                                    unsigned long long b,
                                                    unsigned long long c) {
    unsigned long long d;
    asm("fma.rn.f32x2 %0, %1, %2, %3;" : "=l"(d) : "l"(a), "l"(b), "l"(c));
    return d;
}
__device__ __forceinline__ float sigm(float x) {
    return __fdividef(1.f, 1.f + __expf(-x));
}
__device__ __forceinline__ float tanh_(float x) {
    // 2*sigmoid(2x)-1 : overflow-safe at both ends
    return __fdividef(2.f, 1.f + __expf(-2.f * x)) - 1.f;
}

// ============================================================================
// K1: fused 1x1-conv (GEMM M=589824, N=32, K=72) + LSTM cell update.
// Thread: 1 pixel-quad (4 px as 2 f32x2) x 16 gate-outputs (half of 32).
// Gate slot layout per half h: j in [0,16), gate t=j/4, channel c=h*4+(j%4),
// original o = t*8 + c. So each thread owns i,f,g,o of 4 channels -> local
// LSTM epilogue, float4 coalesced stores of hidden_new / cell_new.
// ============================================================================
__global__ __launch_bounds__(256, 2) void k1_gates(
    const float* __restrict__ x, const float* __restrict__ hidden,
    const float* __restrict__ cell, const float* __restrict__ w_rnn,
    const float* __restrict__ b_rnn,
    float* __restrict__ hid_out, float* __restrict__ cell_out)
{
    __shared__ __align__(16) float2 w2[KTOT * 32];  // [k][slot] duplicated weights
    __shared__ float bias_s[32];

    int tid = threadIdx.x;
    // build duplicated, gate-permuted weights
    for (int idx = tid; idx < KTOT * 32; idx += 256) {
        int k = idx >> 5;
        int s = idx & 31;
        int h = s >> 4;
        int j = s & 15;
        int o = ((j >> 2) << 3) + (h << 2) + (j & 3);
        float w = w_rnn[o * KTOT + k];
        w2[idx] = make_float2(w, w);
    }
    if (tid < 32) {
        int h = tid >> 4, j = tid & 15;
        int o = ((j >> 2) << 3) + (h << 2) + (j & 3);
        bias_s[tid] = b_rnn[o];
    }
    if (blockIdx.x == 0 && tid < 96) g_uvsum[tid] = 0.f;  // zero reduction scratch
    __syncthreads();

    int G = blockIdx.x * 256 + tid;
    int lane = G & 31;
    int half = (G >> 5) & 1;               // constant per warp
    int q = lane + ((G >> 6) << 5);        // quad index 0..147455
    int b = q / QPB;
    int p0 = (q - b * QPB) * 4;

    const float* xb = x + (size_t)b * Cn * HW + p0;
    const float* hb = hidden + (size_t)b * HCH * HW + p0;

    unsigned long long acc[32];
#pragma unroll
    for (int i = 0; i < 32; i++) acc[i] = 0ull;

#pragma unroll 2
    for (int k = 0; k < Cn; k++) {
        float4 xv = *reinterpret_cast<const float4*>(xb + (size_t)k * HW);
        unsigned long long a0 = pack2(xv.x, xv.y);
        unsigned long long a1 = pack2(xv.z, xv.w);
        const ulonglong2* wp =
            reinterpret_cast<const ulonglong2*>(w2 + k * 32 + half * 16);
#pragma unroll
        for (int o2 = 0; o2 < 8; o2++) {
            ulonglong2 ww = wp[o2];
            int j = o2 * 2;
            acc[j]      = ffma2(a0, ww.x, acc[j]);
            acc[j + 1]  = ffma2(a0, ww.y, acc[j + 1]);
            acc[16 + j]     = ffma2(a1, ww.x, acc[16 + j]);
            acc[16 + j + 1] = ffma2(a1, ww.y, acc[16 + j + 1]);
        }
    }
#pragma unroll
    for (int kk = 0; kk < HCH; kk++) {
        int k = Cn + kk;
        float4 xv = *reinterpret_cast<const float4*>(hb + (size_t)kk * HW);
        unsigned long long a0 = pack2(xv.x, xv.y);
        unsigned long long a1 = pack2(xv.z, xv.w);
        const ulonglong2* wp =
            reinterpret_cast<const ulonglong2*>(w2 + k * 32 + half * 16);
#pragma unroll
        for (int o2 = 0; o2 < 8; o2++) {
            ulonglong2 ww = wp[o2];
            int j = o2 * 2;
            acc[j]      = ffma2(a0, ww.x, acc[j]);
            acc[j + 1]  = ffma2(a0, ww.y, acc[j + 1]);
            acc[16 + j]     = ffma2(a1, ww.x, acc[16 + j]);
            acc[16 + j + 1] = ffma2(a1, ww.y, acc[16 + j + 1]);
        }
    }

    // epilogue: per channel cc, 4 pixels
    size_t base = (size_t)b * HCH * HW + p0;
#pragma unroll
    for (int cc = 0; cc < 4; cc++) {
        int c = half * 4 + cc;
        float2 giA = unpack2(acc[cc]);           // pixels 0,1
        float2 giB = unpack2(acc[16 + cc]);      // pixels 2,3
        float2 gfA = unpack2(acc[4 + cc]);
        float2 gfB = unpack2(acc[20 + cc]);
        float2 ggA = unpack2(acc[8 + cc]);
        float2 ggB = unpack2(acc[24 + cc]);
        float2 goA = unpack2(acc[12 + cc]);
        float2 goB = unpack2(acc[28 + cc]);
        float bi = bias_s[half * 16 + cc];
        float bf = bias_s[half * 16 + 4 + cc];
        float bg = bias_s[half * 16 + 8 + cc];
        float bo = bias_s[half * 16 + 12 + cc];

        float4 cv = *reinterpret_cast<const float4*>(cell + base + (size_t)c * HW);

        float4 cn, hn;
        cn.x = sigm(gfA.x + bf) * cv.x + sigm(giA.x + bi) * tanh_(ggA.x + bg);
        cn.y = sigm(gfA.y + bf) * cv.y + sigm(giA.y + bi) * tanh_(ggA.y + bg);
        cn.z = sigm(gfB.x + bf) * cv.z + sigm(giB.x + bi) * tanh_(ggB.x + bg);
        cn.w = sigm(gfB.y + bf) * cv.w + sigm(giB.y + bi) * tanh_(ggB.y + bg);
        hn.x = sigm(goA.x + bo) * tanh_(cn.x);
        hn.y = sigm(goA.y + bo) * tanh_(cn.y);
        hn.z = sigm(goB.x + bo) * tanh_(cn.z);
        hn.w = sigm(goB.y + bo) * tanh_(cn.w);

        *reinterpret_cast<float4*>(cell_out + base + (size_t)c * HW) = cn;
        *reinterpret_cast<float4*>(hid_out  + base + (size_t)c * HW) = hn;
    }
}

// ============================================================================
// K2: 7x7 VALID conv (2 out ch) on hidden_new + sigmoid + partial sums into
// g_uvsum. Block = (batch, 8-row tile), 192 threads (one per column).
// Column-accumulation: each loaded value feeds up to 7 output rows; all
// range predicates are compile-time (full unroll) -> no wasted FMAs.
// ============================================================================
__global__ __launch_bounds__(192) void k2_conv(
    const float* __restrict__ hid, const float* __restrict__ w_conv,
    const float* __restrict__ b_conv)
{
    __shared__ float hsh[14][192];
    __shared__ float wsh[2][8][7][7];
    __shared__ float su[3], sv[3];

    int tid = threadIdx.x;
    int b = blockIdx.x / 24;
    int tile = blockIdx.x - b * 24;
    int r0 = tile * 8;

    for (int i = tid; i < 784; i += 192) ((float*)wsh)[i] = w_conv[i];
    if (tid < 3) su[tid] = 0.f;
    if (tid >= 3 && tid < 6) sv[tid - 3] = 0.f;

    float acc0[8], acc1[8];
#pragma unroll
    for (int y = 0; y < 8; y++) { acc0[y] = 0.f; acc1[y] = 0.f; }

    const float* hb = hid + (size_t)b * HCH * HW;
    for (int c = 0; c < HCH; c++) {
        __syncthreads();
        const float* hc = hb + (size_t)c * HW;
#pragma unroll
        for (int rr = 0; rr < 14; rr++) {
            int r = r0 + rr;
            hsh[rr][tid] = (r < Hn) ? hc[r * Wn + tid] : 0.f;
        }
        __syncthreads();
        if (tid < 186) {
            for (int kx = 0; kx < 7; kx++) {
                float w0r[7], w1r[7];
#pragma unroll
                for (int t = 0; t < 7; t++) {
                    w0r[t] = wsh[0][c][t][kx];
                    w1r[t] = wsh[1][c][t][kx];
                }
#pragma unroll
                for (int rr = 0; rr < 14; rr++) {
                    float v = hsh[rr][tid + kx];
#pragma unroll
                    for (int t = 0; t < 7; t++) {
                        int y = rr - t;
                        if (y >= 0 && y < 8) {
                            acc0[y] += w0r[t] * v;
                            acc1[y] += w1r[t] * v;
                        }
                    }
                }
            }
        }
    }
    __syncthreads();

    float bc0 = b_conv[0], bc1 = b_conv[1];
    if (tid < 186) {
        int ub = tid / 62;
        float usum = 0.f;
        float vsum[3] = {0.f, 0.f, 0.f};
#pragma unroll
        for (int y = 0; y < 8; y++) {
            int row = r0 + y;
            if (row < 186) {
                float s0 = sigm(acc0[y] + bc0);
                float s1 = sigm(acc1[y] + bc1);
                usum += s0;
                vsum[row / 62] += s1;
            }
        }
        atomicAdd(&su[ub], usum);
#pragma unroll
        for (int k = 0; k < 3; k++)
            if (vsum[k] != 0.f) atomicAdd(&sv[k], vsum[k]);
    }
    __syncthreads();
    if (tid < 3) atomicAdd(&g_uvsum[b * 3 + tid], su[tid]);
    if (tid >= 3 && tid < 6) atomicAdd(&g_uvsum[48 + b * 3 + (tid - 3)], sv[tid - 3]);
}

// ============================================================================
// K3: z = vertical(v) o horizontal(u) 3-tap stencil on x (zero padded).
// Thread: 8 output rows x 4 cols of one (b,c) plane; rolling 3-row y window.
// ============================================================================
__device__ __forceinline__ float4 yrow(const float* __restrict__ xp, int r,
                                       int w0, float u0, float u1, float u2) {
    if (r < 0 || r >= Hn) return make_float4(0.f, 0.f, 0.f, 0.f);
    const float* row = xp + r * Wn;
    float4 xv = *reinterpret_cast<const float4*>(row + w0);
    float xl = (w0 > 0) ? row[w0 - 1] : 0.f;
    float xr = (w0 + 4 < Wn) ? row[w0 + 4] : 0.f;
    float4 y;
    y.x = u0 * xl   + u1 * xv.x + u2 * xv.y;
    y.y = u0 * xv.x + u1 * xv.y + u2 * xv.z;
    y.z = u0 * xv.y + u1 * xv.z + u2 * xv.w;
    y.w = u0 * xv.z + u1 * xv.w + u2 * xr;
    return y;
}

__global__ __launch_bounds__(256) void k3_apply(const float* __restrict__ x,
                                                float* __restrict__ z)
{
    int t = blockIdx.x * 256 + threadIdx.x;   // exact grid: 1,179,648 threads
    int cg = t % 48;
    int rs = (t / 48) % 24;
    int plane = t / (48 * 24);
    int b = plane >> 6;
    int w0 = cg * 4;
    int r0 = rs * 8;

    const float inv = 1.f / 11532.f;   // 186 * 62
    float u0 = g_uvsum[b * 3 + 0] * inv;
    float u1 = g_uvsum[b * 3 + 1] * inv;
    float u2 = g_uvsum[b * 3 + 2] * inv;
    float v0 = g_uvsum[48 + b * 3 + 0] * inv;
    float v1 = g_uvsum[48 + b * 3 + 1] * inv;
    float v2 = g_uvsum[48 + b * 3 + 2] * inv;

    const float* xp = x + (size_t)plane * HW;
    float* zp = z + (size_t)plane * HW;

    float4 ya = yrow(xp, r0 - 1, w0, u0, u1, u2);
    float4 yb = yrow(xp, r0,     w0, u0, u1, u2);
#pragma unroll
    for (int i = 0; i < 8; i++) {
        float4 yc = yrow(xp, r0 + i + 1, w0, u0, u1, u2);
        float4 zo;
        zo.x = v0 * ya.x + v1 * yb.x + v2 * yc.x;
        zo.y = v0 * ya.y + v1 * yb.y + v2 * yc.y;
        zo.z = v0 * ya.z + v1 * yb.z + v2 * yc.z;
        zo.w = v0 * ya.w + v1 * yb.w + v2 * yc.w;
        *reinterpret_cast<float4*>(zp + (r0 + i) * Wn + w0) = zo;
        ya = yb;
        yb = yc;
    }
}

// ============================================================================
extern "C" void kernel_launch(void* const* d_in, const int* in_sizes, int n_in,
                              void* d_out, int out_size)
{
    const float* x      = (const float*)d_in[0];
    const float* hidden = (const float*)d_in[1];
    const float* cell   = (const float*)d_in[2];
    const float* w_rnn  = (const float*)d_in[3];
    const float* b_rnn  = (const float*)d_in[4];
    const float* w_conv = (const float*)d_in[5];
    const float* b_conv = (const float*)d_in[6];
    float* z = (float*)d_out;

    float* hid_out;
    float* cell_out;
    if (out_size >= Z_ELEMS + 2 * HC_ELEMS) {
        hid_out  = z + Z_ELEMS;
        cell_out = z + Z_ELEMS + HC_ELEMS;
    } else {
        void* p0 = nullptr; void* p1 = nullptr;
        cudaGetSymbolAddress(&p0, g_hid_scratch);
        cudaGetSymbolAddress(&p1, g_cell_scratch);
        hid_out  = (float*)p0;
        cell_out = (float*)p1;
    }

    k1_gates<<<1152, 256>>>(x, hidden, cell, w_rnn, b_rnn, hid_out, cell_out);
    k2_conv<<<Bn * 24, 192>>>(hid_out, w_conv, b_conv);
    k3_apply<<<4608, 256>>>(x, z);
}

// round 3
// speedup vs baseline: 1.0085x; 1.0085x over previous
#include <cuda_runtime.h>
#include <cstdint>

#define Bn 16
#define Cn 64
#define Hn 192
#define Wn 192
#define HCH 8
#define HW (Hn*Wn)                 // 36864
#define Z_ELEMS (Bn*Cn*HW)         // 37748736
#define HC_ELEMS (Bn*HCH*HW)       // 4718592
#define KTOT (Cn + HCH)            // 72
#define QPB  (HW/4)                // pixel-quads per batch = 9216

__device__ float g_uvsum[96];
__device__ float g_hid_scratch[HC_ELEMS];
__device__ float g_cell_scratch[HC_ELEMS];

// ---------- helpers ----------
__device__ __forceinline__ unsigned long long pack2(float lo, float hi) {
    unsigned long long r;
    asm("mov.b64 %0, {%1, %2};" : "=l"(r) : "f"(lo), "f"(hi));
    return r;
}
__device__ __forceinline__ float2 unpack2(unsigned long long v) {
    float lo, hi;
    asm("mov.b64 {%0, %1}, %2;" : "=f"(lo), "=f"(hi) : "l"(v));
    return make_float2(lo, hi);
}
__device__ __forceinline__ unsigned long long ffma2(unsigned long long a,
                                                    unsigned long long b,
                                                    unsigned long long c) {
    unsigned long long d;
    asm("fma.rn.f32x2 %0, %1, %2, %3;" : "=l"(d) : "l"(a), "l"(b), "l"(c));
    return d;
}
__device__ __forceinline__ float sigm(float x) {
    return __fdividef(1.f, 1.f + __expf(-x));
}
__device__ __forceinline__ float tanh_(float x) {
    return __fdividef(2.f, 1.f + __expf(-2.f * x)) - 1.f;
}

// ============================================================================
// K1: fused 1x1-conv GEMM (M=589824, N=32, K=72) + LSTM cell update.
// Thread: 1 pixel-quad x 8 gate-outputs (quarter of 32): i,f,g,o of 2 channels.
// acc = 16 x b64 (f32x2) -> 32 regs; 3 CTAs/SM (24 warps) for latency hiding.
// Slot layout: s = qt*8 + j ; gate t = j>>1 ; channel c = qt*2 + (j&1);
// original o = t*8 + c. Warps 4i..4i+3 of the grid share the same 32 quads
// (qt = bits[5:6] of G) -> x loads hit L1 3/4 of the time.
// ============================================================================
__global__ __launch_bounds__(256, 3) void k1_gates(
    const float* __restrict__ x, const float* __restrict__ hidden,
    const float* __restrict__ cell, const float* __restrict__ w_rnn,
    const float* __restrict__ b_rnn,
    float* __restrict__ hid_out, float* __restrict__ cell_out)
{
    __shared__ __align__(16) float2 w2[KTOT * 32];  // [k][slot] duplicated
    __shared__ float bias_s[32];

    int tid = threadIdx.x;
    for (int idx = tid; idx < KTOT * 32; idx += 256) {
        int k = idx >> 5;
        int s = idx & 31;
        int qt = s >> 3, j = s & 7;
        int o = ((j >> 1) << 3) + qt * 2 + (j & 1);
        float w = w_rnn[o * KTOT + k];
        w2[idx] = make_float2(w, w);
    }
    if (tid < 32) {
        int qt = tid >> 3, j = tid & 7;
        int o = ((j >> 1) << 3) + qt * 2 + (j & 1);
        bias_s[tid] = b_rnn[o];
    }
    if (blockIdx.x == 0 && tid < 96) g_uvsum[tid] = 0.f;
    __syncthreads();

    int G = blockIdx.x * 256 + tid;
    int lane = G & 31;
    int qt = (G >> 5) & 3;                 // warp-uniform
    int q = lane + ((G >> 7) << 5);        // quad 0..147455
    int b = q / QPB;
    int p0 = (q - b * QPB) * 4;

    const float* xb = x + (size_t)b * Cn * HW + p0;
    const float* hb = hidden + (size_t)b * HCH * HW + p0;

    unsigned long long acc[16];
#pragma unroll
    for (int i = 0; i < 16; i++) acc[i] = 0ull;

    const ulonglong2* wrow = reinterpret_cast<const ulonglong2*>(w2) + qt * 4;

#pragma unroll 4
    for (int k = 0; k < Cn; k++) {
        float4 xv = *reinterpret_cast<const float4*>(xb);
        xb += HW;
        unsigned long long a0 = pack2(xv.x, xv.y);
        unsigned long long a1 = pack2(xv.z, xv.w);
        ulonglong2 wA = wrow[0], wB = wrow[1], wC = wrow[2], wD = wrow[3];
        wrow += 16;
        acc[0]  = ffma2(a0, wA.x, acc[0]);   acc[8]  = ffma2(a1, wA.x, acc[8]);
        acc[1]  = ffma2(a0, wA.y, acc[1]);   acc[9]  = ffma2(a1, wA.y, acc[9]);
        acc[2]  = ffma2(a0, wB.x, acc[2]);   acc[10] = ffma2(a1, wB.x, acc[10]);
        acc[3]  = ffma2(a0, wB.y, acc[3]);   acc[11] = ffma2(a1, wB.y, acc[11]);
        acc[4]  = ffma2(a0, wC.x, acc[4]);   acc[12] = ffma2(a1, wC.x, acc[12]);
        acc[5]  = ffma2(a0, wC.y, acc[5]);   acc[13] = ffma2(a1, wC.y, acc[13]);
        acc[6]  = ffma2(a0, wD.x, acc[6]);   acc[14] = ffma2(a1, wD.x, acc[14]);
        acc[7]  = ffma2(a0, wD.y, acc[7]);   acc[15] = ffma2(a1, wD.y, acc[15]);
    }
#pragma unroll
    for (int kk = 0; kk < HCH; kk++) {
        float4 xv = *reinterpret_cast<const float4*>(hb);
        hb += HW;
        unsigned long long a0 = pack2(xv.x, xv.y);
        unsigned long long a1 = pack2(xv.z, xv.w);
        ulonglong2 wA = wrow[0], wB = wrow[1], wC = wrow[2], wD = wrow[3];
        wrow += 16;
        acc[0]  = ffma2(a0, wA.x, acc[0]);   acc[8]  = ffma2(a1, wA.x, acc[8]);
        acc[1]  = ffma2(a0, wA.y, acc[1]);   acc[9]  = ffma2(a1, wA.y, acc[9]);
        acc[2]  = ffma2(a0, wB.x, acc[2]);   acc[10] = ffma2(a1, wB.x, acc[10]);
        acc[3]  = ffma2(a0, wB.y, acc[3]);   acc[11] = ffma2(a1, wB.y, acc[11]);
        acc[4]  = ffma2(a0, wC.x, acc[4]);   acc[12] = ffma2(a1, wC.x, acc[12]);
        acc[5]  = ffma2(a0, wC.y, acc[5]);   acc[13] = ffma2(a1, wC.y, acc[13]);
        acc[6]  = ffma2(a0, wD.x, acc[6]);   acc[14] = ffma2(a1, wD.x, acc[14]);
        acc[7]  = ffma2(a0, wD.y, acc[7]);   acc[15] = ffma2(a1, wD.y, acc[15]);
    }

    // epilogue: channels c = qt*2 + cc, 4 pixels each
    size_t base = (size_t)b * HCH * HW + p0;
#pragma unroll
    for (int cc = 0; cc < 2; cc++) {
        int c = qt * 2 + cc;
        float2 giA = unpack2(acc[cc]);           // px 0,1
        float2 giB = unpack2(acc[8 + cc]);       // px 2,3
        float2 gfA = unpack2(acc[2 + cc]);
        float2 gfB = unpack2(acc[10 + cc]);
        float2 ggA = unpack2(acc[4 + cc]);
        float2 ggB = unpack2(acc[12 + cc]);
        float2 goA = unpack2(acc[6 + cc]);
        float2 goB = unpack2(acc[14 + cc]);
        float bi = bias_s[qt * 8 + cc];
        float bf = bias_s[qt * 8 + 2 + cc];
        float bg = bias_s[qt * 8 + 4 + cc];
        float bo = bias_s[qt * 8 + 6 + cc];

        float4 cv = *reinterpret_cast<const float4*>(cell + base + (size_t)c * HW);

        float4 cn, hn;
        cn.x = sigm(gfA.x + bf) * cv.x + sigm(giA.x + bi) * tanh_(ggA.x + bg);
        cn.y = sigm(gfA.y + bf) * cv.y + sigm(giA.y + bi) * tanh_(ggA.y + bg);
        cn.z = sigm(gfB.x + bf) * cv.z + sigm(giB.x + bi) * tanh_(ggB.x + bg);
        cn.w = sigm(gfB.y + bf) * cv.w + sigm(giB.y + bi) * tanh_(ggB.y + bg);
        hn.x = sigm(goA.x + bo) * tanh_(cn.x);
        hn.y = sigm(goA.y + bo) * tanh_(cn.y);
        hn.z = sigm(goB.x + bo) * tanh_(cn.z);
        hn.w = sigm(goB.y + bo) * tanh_(cn.w);

        *reinterpret_cast<float4*>(cell_out + base + (size_t)c * HW) = cn;
        *reinterpret_cast<float4*>(hid_out  + base + (size_t)c * HW) = hn;
    }
}

// ============================================================================
// K2: 7x7 VALID conv (2 out ch packed into f32x2) + sigmoid + partial sums.
// Block = (batch, 8-row tile), 192 threads (one per column).
// ============================================================================
__global__ __launch_bounds__(192) void k2_conv(
    const float* __restrict__ hid, const float* __restrict__ w_conv,
    const float* __restrict__ b_conv)
{
    __shared__ float hsh[14][192];
    __shared__ float wsh[2][8][7][7];
    __shared__ float su[3], sv[3];

    int tid = threadIdx.x;
    int b = blockIdx.x / 24;
    int tile = blockIdx.x - b * 24;
    int r0 = tile * 8;

    for (int i = tid; i < 784; i += 192) ((float*)wsh)[i] = w_conv[i];
    if (tid < 3) su[tid] = 0.f;
    if (tid >= 3 && tid < 6) sv[tid - 3] = 0.f;

    unsigned long long accp[8];            // {ch0, ch1} per output row
#pragma unroll
    for (int y = 0; y < 8; y++) accp[y] = 0ull;

    const float* hb = hid + (size_t)b * HCH * HW;
    for (int c = 0; c < HCH; c++) {
        __syncthreads();
        const float* hc = hb + (size_t)c * HW;
#pragma unroll
        for (int rr = 0; rr < 14; rr++) {
            int r = r0 + rr;
            hsh[rr][tid] = (r < Hn) ? hc[r * Wn + tid] : 0.f;
        }
        __syncthreads();
        if (tid < 186) {
            for (int kx = 0; kx < 7; kx++) {
                unsigned long long wp_[7];
#pragma unroll
                for (int t = 0; t < 7; t++)
                    wp_[t] = pack2(wsh[0][c][t][kx], wsh[1][c][t][kx]);
#pragma unroll
                for (int rr = 0; rr < 14; rr++) {
                    float v = hsh[rr][tid + kx];
                    unsigned long long vv = pack2(v, v);
#pragma unroll
                    for (int t = 0; t < 7; t++) {
                        int y = rr - t;
                        if (y >= 0 && y < 8)
                            accp[y] = ffma2(vv, wp_[t], accp[y]);
                    }
                }
            }
        }
    }
    __syncthreads();

    float bc0 = b_conv[0], bc1 = b_conv[1];
    if (tid < 186) {
        int ub = tid / 62;
        float usum = 0.f;
        float vsum[3] = {0.f, 0.f, 0.f};
#pragma unroll
        for (int y = 0; y < 8; y++) {
            int row = r0 + y;
            if (row < 186) {
                float2 a = unpack2(accp[y]);
                float s0 = sigm(a.x + bc0);
                float s1 = sigm(a.y + bc1);
                usum += s0;
                vsum[row / 62] += s1;
            }
        }
        atomicAdd(&su[ub], usum);
#pragma unroll
        for (int k = 0; k < 3; k++)
            if (vsum[k] != 0.f) atomicAdd(&sv[k], vsum[k]);
    }
    __syncthreads();
    if (tid < 3) atomicAdd(&g_uvsum[b * 3 + tid], su[tid]);
    if (tid >= 3 && tid < 6) atomicAdd(&g_uvsum[48 + b * 3 + (tid - 3)], sv[tid - 3]);
}

// ============================================================================
// K3: z = vertical(v) o horizontal(u) 3-tap stencil on x (zero padded).
// Thread: 16 rows x 16 cols of one (b,c) plane; rolling 3-row y window.
// ============================================================================
struct Y16 { float4 v[4]; };

__device__ __forceinline__ Y16 yrow16(const float* __restrict__ xp, int r,
                                      int w0, float u0, float u1, float u2) {
    Y16 y;
    if (r < 0 || r >= Hn) {
#pragma unroll
        for (int i = 0; i < 4; i++) y.v[i] = make_float4(0.f, 0.f, 0.f, 0.f);
        return y;
    }
    const float* row = xp + r * Wn;
    float4 xv[4];
#pragma unroll
    for (int i = 0; i < 4; i++)
        xv[i] = *reinterpret_cast<const float4*>(row + w0 + i * 4);
    float xl = (w0 > 0) ? row[w0 - 1] : 0.f;
    float xr = (w0 + 16 < Wn) ? row[w0 + 16] : 0.f;
#pragma unroll
    for (int i = 0; i < 4; i++) {
        float l  = (i == 0) ? xl : xv[i - 1].w;
        float rr = (i == 3) ? xr : xv[i + 1].x;
        y.v[i].x = u0 * l       + u1 * xv[i].x + u2 * xv[i].y;
        y.v[i].y = u0 * xv[i].x + u1 * xv[i].y + u2 * xv[i].z;
        y.v[i].z = u0 * xv[i].y + u1 * xv[i].z + u2 * xv[i].w;
        y.v[i].w = u0 * xv[i].z + u1 * xv[i].w + u2 * rr;
    }
    return y;
}

__global__ __launch_bounds__(256) void k3_apply(const float* __restrict__ x,
                                                float* __restrict__ z)
{
    int t = blockIdx.x * 256 + threadIdx.x;   // 147456 threads total
    int cg = t % 12;
    int rs = (t / 12) % 12;
    int plane = t / 144;
    int b = plane >> 6;
    int w0 = cg * 16;
    int r0 = rs * 16;

    const float inv = 1.f / 11532.f;   // 186 * 62
    float u0 = g_uvsum[b * 3 + 0] * inv;
    float u1 = g_uvsum[b * 3 + 1] * inv;
    float u2 = g_uvsum[b * 3 + 2] * inv;
    float v0 = g_uvsum[48 + b * 3 + 0] * inv;
    float v1 = g_uvsum[48 + b * 3 + 1] * inv;
    float v2 = g_uvsum[48 + b * 3 + 2] * inv;

    const float* xp = x + (size_t)plane * HW;
    float* zp = z + (size_t)plane * HW;

    Y16 ya = yrow16(xp, r0 - 1, w0, u0, u1, u2);
    Y16 yb = yrow16(xp, r0,     w0, u0, u1, u2);
#pragma unroll
    for (int i = 0; i < 16; i++) {
        Y16 yc = yrow16(xp, r0 + i + 1, w0, u0, u1, u2);
        float* zr = zp + (r0 + i) * Wn + w0;
#pragma unroll
        for (int j = 0; j < 4; j++) {
            float4 zo;
            zo.x = v0 * ya.v[j].x + v1 * yb.v[j].x + v2 * yc.v[j].x;
            zo.y = v0 * ya.v[j].y + v1 * yb.v[j].y + v2 * yc.v[j].y;
            zo.z = v0 * ya.v[j].z + v1 * yb.v[j].z + v2 * yc.v[j].z;
            zo.w = v0 * ya.v[j].w + v1 * yb.v[j].w + v2 * yc.v[j].w;
            *reinterpret_cast<float4*>(zr + j * 4) = zo;
        }
        ya = yb;
        yb = yc;
    }
}

// ============================================================================
extern "C" void kernel_launch(void* const* d_in, const int* in_sizes, int n_in,
                              void* d_out, int out_size)
{
    const float* x      = (const float*)d_in[0];
    const float* hidden = (const float*)d_in[1];
    const float* cell   = (const float*)d_in[2];
    const float* w_rnn  = (const float*)d_in[3];
    const float* b_rnn  = (const float*)d_in[4];
    const float* w_conv = (const float*)d_in[5];
    const float* b_conv = (const float*)d_in[6];
    float* z = (float*)d_out;

    float* hid_out;
    float* cell_out;
    if (out_size >= Z_ELEMS + 2 * HC_ELEMS) {
        hid_out  = z + Z_ELEMS;
        cell_out = z + Z_ELEMS + HC_ELEMS;
    } else {
        void* p0 = nullptr; void* p1 = nullptr;
        cudaGetSymbolAddress(&p0, g_hid_scratch);
        cudaGetSymbolAddress(&p1, g_cell_scratch);
        hid_out  = (float*)p0;
        cell_out = (float*)p1;
    }

    k1_gates<<<2304, 256>>>(x, hidden, cell, w_rnn, b_rnn, hid_out, cell_out);
    k2_conv<<<Bn * 24, 192>>>(hid_out, w_conv, b_conv);
    k3_apply<<<576, 256>>>(x, z);
}